// round 15
// baseline (speedup 1.0000x reference)
#include <cuda_runtime.h>
#include <cstdint>

// FP8 (E4M3 bit-vector of 0.0/1.0 floats) -> FP32 bit-vector.
// In : 4194304 rows x 8 floats  [s, e3, e2, e1, e0, m2, m1, m0]
// Out: 4194304 rows x 32 floats [s, exp7..exp0, mant22..mant0]
// Only outputs 0..11 per row can be nonzero.
//
// FINAL, converged. 7-run band 104.45-106.5us (same-source spread ~2us =
// harness noise); kernel-internal ~100us at 6.0-6.16 TB/s == exactly the
// compulsory 640MB of traffic (zero wasted bytes); DRAM 74-75% == achieved
// HBM ceiling for a 1:4 read:write stream (invariant across 6 structural
// variants; persistent 1-wave variant measured 19% WORSE).
//
// Strategy: many independent CTAs (cross-CTA load/store overlap), smem-staged
// so both global loads and stores are fully coalesced (consecutive lanes ->
// consecutive 16B chunks), evict-first stores.

#define TPB 256   // threads per block == rows per block

__device__ __forceinline__ uint32_t fp32_word(uint4 A, uint4 B)
{
    // 1.0f == 0x3F800000 -> test bit 29.
    uint32_t s = (A.x >> 29) & 1u;
    uint32_t e = ((A.y >> 26) & 8u) | ((A.z >> 27) & 4u) |
                 ((A.w >> 28) & 2u) | ((B.x >> 29) & 1u);
    uint32_t m = ((B.y >> 27) & 4u) | ((B.z >> 28) & 2u) |
                 ((B.w >> 29) & 1u);

    uint32_t expf, mant;
    if (e != 0u) {                 // normal (incl. NaN pattern, as reference)
        expf = e + 120u;
        mant = m << 20;
    } else if (m & 4u) {           // subnormal 1xx
        expf = 120u;
        mant = (m & 3u) << 21;
    } else if (m & 2u) {           // subnormal 01x
        expf = 119u;
        mant = (m & 1u) << 22;
    } else if (m != 0u) {          // subnormal 001
        expf = 118u;
        mant = 0u;
    } else {                       // true zero
        expf = 0u;
        mant = 0u;
    }
    return (s << 31) | (expf << 23) | mant;   // bits 19..0 == 0
}

template <bool FULL>
__global__ void __launch_bounds__(TPB)
fp8_to_fp32_bits_kernel(const uint4* __restrict__ in,
                        uint4* __restrict__ out,
                        int nrows)
{
    __shared__ uint4    s_in[2 * TPB];   // 256 rows x 32B = 8KB
    __shared__ uint32_t s_w[TPB];        // one fp32 bit-word per row

    const int t = threadIdx.x;
    const size_t rowBase = (size_t)blockIdx.x * TPB;
    const int rowsHere = FULL ? TPB : min(TPB, nrows - (int)rowBase);

    // ---- Phase 1: coalesced global loads into smem (contiguous 8KB) ----
    const uint4* gin = in + rowBase * 2;
    if (FULL || t < 2 * rowsHere)        s_in[t]       = gin[t];
    if (FULL || t + TPB < 2 * rowsHere)  s_in[t + TPB] = gin[t + TPB];
    __syncthreads();

    // ---- Phase 2: one thread per row computes the fp32 bit word ----
    if (FULL || t < rowsHere)
        s_w[t] = fp32_word(s_in[2 * t], s_in[2 * t + 1]);
    __syncthreads();

    // ---- Phase 3: coalesced, evict-first global stores (32KB/block) ----
    uint4* gout = out + rowBase * 8;
    const uint32_t ONE = 0x3F800000u;
    const int chunksHere = 8 * rowsHere;

    #pragma unroll
    for (int k = 0; k < 8; k++) {
        int idx  = k * TPB + t;
        if (!FULL && idx >= chunksHere) break;
        int row  = idx >> 3;           // which row this 16B chunk belongs to
        int part = idx & 7;            // which of the 8 chunks in the row
        uint4 v = make_uint4(0u, 0u, 0u, 0u);
        if (part < 3) {
            uint32_t w  = s_w[row];    // broadcast across the 8 lanes of a row
            int sh = 31 - part * 4;    // chunk0: 31..28, chunk1: 27..24, chunk2: 23..20
            v.x = ((w >> sh)       & 1u) * ONE;
            v.y = ((w >> (sh - 1)) & 1u) * ONE;
            v.z = ((w >> (sh - 2)) & 1u) * ONE;
            v.w = ((w >> (sh - 3)) & 1u) * ONE;
        }
        __stcs(&gout[idx], v);
    }
}

extern "C" void kernel_launch(void* const* d_in, const int* in_sizes, int n_in,
                              void* d_out, int out_size)
{
    const uint4* in  = (const uint4*)d_in[0];
    uint4*       out = (uint4*)d_out;
    int nrows = in_sizes[0] / 8;              // 4194304

    int fullBlocks = nrows / TPB;             // 16384
    int remRows    = nrows % TPB;

    if (fullBlocks > 0)
        fp8_to_fp32_bits_kernel<true><<<fullBlocks, TPB>>>(in, out, nrows);
    if (remRows > 0)
        fp8_to_fp32_bits_kernel<false><<<1, TPB>>>(
            in + (size_t)fullBlocks * TPB * 2,
            out + (size_t)fullBlocks * TPB * 8,
            remRows);
}

// round 16
// speedup vs baseline: 1.0003x; 1.0003x over previous
#include <cuda_runtime.h>
#include <cstdint>

// FP8 (E4M3 bit-vector of 0.0/1.0 floats) -> FP32 bit-vector.
// In : 4194304 rows x 8 floats  [s, e3, e2, e1, e0, m2, m1, m0]
// Out: 4194304 rows x 32 floats [s, exp7..exp0, mant22..mant0]
// Only outputs 0..11 per row can be nonzero.
//
// FINAL, converged. 8-run band 104.45-106.5us (same-source spread ~2us =
// harness noise); kernel-internal ~99-101us at 6.0-6.16 TB/s == exactly the
// compulsory 640MB of traffic (zero wasted bytes); DRAM 74-75% == achieved
// HBM ceiling for a 1:4 read:write stream (invariant across 6 structural
// variants; persistent 1-wave variant measured 19% WORSE).
//
// Strategy: many independent CTAs (cross-CTA load/store overlap), smem-staged
// so both global loads and stores are fully coalesced (consecutive lanes ->
// consecutive 16B chunks), evict-first stores.

#define TPB 256   // threads per block == rows per block

__device__ __forceinline__ uint32_t fp32_word(uint4 A, uint4 B)
{
    // 1.0f == 0x3F800000 -> test bit 29.
    uint32_t s = (A.x >> 29) & 1u;
    uint32_t e = ((A.y >> 26) & 8u) | ((A.z >> 27) & 4u) |
                 ((A.w >> 28) & 2u) | ((B.x >> 29) & 1u);
    uint32_t m = ((B.y >> 27) & 4u) | ((B.z >> 28) & 2u) |
                 ((B.w >> 29) & 1u);

    uint32_t expf, mant;
    if (e != 0u) {                 // normal (incl. NaN pattern, as reference)
        expf = e + 120u;
        mant = m << 20;
    } else if (m & 4u) {           // subnormal 1xx
        expf = 120u;
        mant = (m & 3u) << 21;
    } else if (m & 2u) {           // subnormal 01x
        expf = 119u;
        mant = (m & 1u) << 22;
    } else if (m != 0u) {          // subnormal 001
        expf = 118u;
        mant = 0u;
    } else {                       // true zero
        expf = 0u;
        mant = 0u;
    }
    return (s << 31) | (expf << 23) | mant;   // bits 19..0 == 0
}

template <bool FULL>
__global__ void __launch_bounds__(TPB)
fp8_to_fp32_bits_kernel(const uint4* __restrict__ in,
                        uint4* __restrict__ out,
                        int nrows)
{
    __shared__ uint4    s_in[2 * TPB];   // 256 rows x 32B = 8KB
    __shared__ uint32_t s_w[TPB];        // one fp32 bit-word per row

    const int t = threadIdx.x;
    const size_t rowBase = (size_t)blockIdx.x * TPB;
    const int rowsHere = FULL ? TPB : min(TPB, nrows - (int)rowBase);

    // ---- Phase 1: coalesced global loads into smem (contiguous 8KB) ----
    const uint4* gin = in + rowBase * 2;
    if (FULL || t < 2 * rowsHere)        s_in[t]       = gin[t];
    if (FULL || t + TPB < 2 * rowsHere)  s_in[t + TPB] = gin[t + TPB];
    __syncthreads();

    // ---- Phase 2: one thread per row computes the fp32 bit word ----
    if (FULL || t < rowsHere)
        s_w[t] = fp32_word(s_in[2 * t], s_in[2 * t + 1]);
    __syncthreads();

    // ---- Phase 3: coalesced, evict-first global stores (32KB/block) ----
    uint4* gout = out + rowBase * 8;
    const uint32_t ONE = 0x3F800000u;
    const int chunksHere = 8 * rowsHere;

    #pragma unroll
    for (int k = 0; k < 8; k++) {
        int idx  = k * TPB + t;
        if (!FULL && idx >= chunksHere) break;
        int row  = idx >> 3;           // which row this 16B chunk belongs to
        int part = idx & 7;            // which of the 8 chunks in the row
        uint4 v = make_uint4(0u, 0u, 0u, 0u);
        if (part < 3) {
            uint32_t w  = s_w[row];    // broadcast across the 8 lanes of a row
            int sh = 31 - part * 4;    // chunk0: 31..28, chunk1: 27..24, chunk2: 23..20
            v.x = ((w >> sh)       & 1u) * ONE;
            v.y = ((w >> (sh - 1)) & 1u) * ONE;
            v.z = ((w >> (sh - 2)) & 1u) * ONE;
            v.w = ((w >> (sh - 3)) & 1u) * ONE;
        }
        __stcs(&gout[idx], v);
    }
}

extern "C" void kernel_launch(void* const* d_in, const int* in_sizes, int n_in,
                              void* d_out, int out_size)
{
    const uint4* in  = (const uint4*)d_in[0];
    uint4*       out = (uint4*)d_out;
    int nrows = in_sizes[0] / 8;              // 4194304

    int fullBlocks = nrows / TPB;             // 16384
    int remRows    = nrows % TPB;

    if (fullBlocks > 0)
        fp8_to_fp32_bits_kernel<true><<<fullBlocks, TPB>>>(in, out, nrows);
    if (remRows > 0)
        fp8_to_fp32_bits_kernel<false><<<1, TPB>>>(
            in + (size_t)fullBlocks * TPB * 2,
            out + (size_t)fullBlocks * TPB * 8,
            remRows);
}